// round 12
// baseline (speedup 1.0000x reference)
#include <cuda_runtime.h>
#include <cstdint>

// CARAFE: N=4, C=256, H=W=64, K=5, G=1, S=2  ->  out [4,256,128,128] f32
#define KK   5
#define N_   4
#define C_   256
#define H_   64
#define W_   64
#define HO   128
#define WO   128

#define TH_CELLS 4         // input cells per CTA (rows)
#define TW_CELLS 8         // input cells per CTA (cols)
#define PR 8               // patch rows = TH_CELLS + 4
#define PC 12              // patch cols = TW_CELLS + 4
#define PS2 24             // row stride in float2 units: mod 16 == 8 -> conflict-free phases
#define PAIR_F (PR * PS2 * 2)     // 384 floats per channel-pair patch
#define STAGE_F (4 * PAIR_F)      // 1536 floats per 8-channel stage
#define NTHREADS 128
#define NCHUNK 2                  // channel split: 2 CTAs per tile
#define CHPC (C_ / NCHUNK)        // 128 channels per CTA
#define NSTAGE (CHPC / 8)         // 16 stages of 8 channels
#define NLOAD (8 * PR * PC)       // 768 feature elements per stage
#define LPT (NLOAD / NTHREADS)    // 6

typedef unsigned long long ull;

__device__ __forceinline__ ull pack2(float lo, float hi) {
    ull r;
    asm("mov.b64 %0, {%1, %2};" : "=l"(r) : "f"(lo), "f"(hi));
    return r;
}
__device__ __forceinline__ void unpack2(float& lo, float& hi, ull v) {
    asm("mov.b64 {%0, %1}, %2;" : "=f"(lo), "=f"(hi) : "l"(v));
}
__device__ __forceinline__ void ffma2(ull& d, ull a, ull b) {
    asm("fma.rn.f32x2 %0, %1, %2, %0;" : "+l"(d) : "l"(a), "l"(b));
}

__global__ void __launch_bounds__(NTHREADS, 4)
carafe_kernel(const float* __restrict__ feat, const float* __restrict__ masks,
              float* __restrict__ out)
{
    __shared__ __align__(16) float sbuf[2][STAGE_F];   // 2*1536*4 = 12288 B

    const int t    = threadIdx.x;
    const int slot = t >> 5;          // 0..3 : channel-pair slot (uniform per warp)
    const int lane = t & 31;          // cell id in 4x8 tile
    const int hh   = lane >> 3;       // 0..3
    const int ww   = lane & 7;        // 0..7

    const int b     = blockIdx.x;     // 0..1023
    const int chunk = b & 1;          // 2 CTAs sharing a tile's masks are adjacent
    const int tidx  = (b >> 1) & 127;
    const int n     = b >> 8;
    const int th    = tidx >> 3;      // 0..15
    const int tw    = tidx & 7;       // 0..7
    const int h0    = th * TH_CELLS;
    const int w0    = tw * TW_CELLS;
    const int oh    = (h0 + hh) * 2;
    const int ow0   = (w0 + ww) * 2;  // even -> 8B-aligned in masks/out

    // ---- per-thread masks: 25 taps x 2 output rows, packed over q ----
    ull m0[25], m1[25];
    {
        const float* mb = masks + (size_t)n * 25 * (HO * WO) + (size_t)oh * WO + ow0;
        #pragma unroll
        for (int k = 0; k < 25; ++k) {
            const float2 a = __ldg((const float2*)(mb + (size_t)k * (HO * WO)));
            const float2 c = __ldg((const float2*)(mb + (size_t)k * (HO * WO) + WO));
            m0[k] = pack2(a.x, a.y);
            m1[k] = pack2(c.x, c.y);
        }
    }

    // ---- cooperative-load slots: interleaved (ch&1) channel-pair layout, stride PS2 ----
    const float* fbase = feat + (size_t)n * (C_ * H_ * W_)
                              + (size_t)chunk * CHPC * (H_ * W_);
    int sofs[LPT], gofs[LPT];
    #pragma unroll
    for (int i = 0; i < LPT; ++i) {
        const int e   = t + i * NTHREADS;          // < 768
        const int ch  = e / (PR * PC);
        const int rem = e - ch * (PR * PC);
        const int r   = rem / PC;
        const int col = rem - r * PC;
        const int gr  = h0 - 2 + r - hh * 0;       // (note: r is patch row, base h0-2)
        const int gc  = w0 - 2 + col;
        sofs[i] = (ch >> 1) * PAIR_F + r * (PS2 * 2) + col * 2 + (ch & 1);
        gofs[i] = ((unsigned)(h0 - 2 + r) < (unsigned)H_ && (unsigned)gc < (unsigned)W_)
                      ? (ch * (H_ * W_) + (h0 - 2 + r) * W_ + gc)
                      : -1;
        (void)gr;
    }

    float v[LPT];

    // prologue: stage 0 -> buffer 0
    #pragma unroll
    for (int i = 0; i < LPT; ++i)
        v[i] = (gofs[i] >= 0) ? __ldg(fbase + gofs[i]) : 0.f;
    #pragma unroll
    for (int i = 0; i < LPT; ++i)
        sbuf[0][sofs[i]] = v[i];
    __syncthreads();

    float* obase = out + (size_t)n * (C_ * HO * WO)
                       + (size_t)chunk * CHPC * (HO * WO)
                       + (size_t)oh * WO + ow0;

    #pragma unroll 1
    for (int s = 0; s < NSTAGE; ++s) {
        // prefetch next stage's features (latency hidden under compute)
        if (s + 1 < NSTAGE) {
            const float* fb = fbase + (size_t)(s + 1) * 8 * (H_ * W_);
            #pragma unroll
            for (int i = 0; i < LPT; ++i)
                v[i] = (gofs[i] >= 0) ? __ldg(fb + gofs[i]) : 0.f;
        }

        // compute: 2 channels x 2x2 outputs; per tap 1 LDS.64 + 2 dup + 4 FFMA2
        const float* sb = &sbuf[s & 1][0] + slot * PAIR_F + (hh * PS2 + ww) * 2;
        ull aC0P0 = 0, aC0P1 = 0, aC1P0 = 0, aC1P1 = 0;
        #pragma unroll
        for (int ki = 0; ki < KK; ++ki) {
            #pragma unroll
            for (int kj = 0; kj < KK; ++kj) {
                const int k = ki * KK + kj;
                const ull f = *(const ull*)(sb + (ki * PS2 + kj) * 2);
                float c0, c1;
                unpack2(c0, c1, f);
                const ull d0 = pack2(c0, c0);
                const ull d1 = pack2(c1, c1);
                ffma2(aC0P0, d0, m0[k]);
                ffma2(aC0P1, d0, m1[k]);
                ffma2(aC1P0, d1, m0[k]);
                ffma2(aC1P1, d1, m1[k]);
            }
        }

        // stores: 2 channels x 2 rows, STG.64 (q-pair), coalesced per row-group
        {
            const int c0 = s * 8 + slot * 2;
            ull* o0 = (ull*)(obase + (size_t)c0 * (HO * WO));
            ull* o1 = (ull*)(obase + (size_t)(c0 + 1) * (HO * WO));
            o0[0]      = aC0P0;
            o0[WO / 2] = aC0P1;   // next output row
            o1[0]      = aC1P0;
            o1[WO / 2] = aC1P1;
        }

        // commit prefetched data to the other buffer
        if (s + 1 < NSTAGE) {
            float* dst = &sbuf[(s + 1) & 1][0];
            #pragma unroll
            for (int i = 0; i < LPT; ++i)
                dst[sofs[i]] = v[i];
        }
        __syncthreads();
    }
}

extern "C" void kernel_launch(void* const* d_in, const int* in_sizes, int n_in,
                              void* d_out, int out_size) {
    const float* feat  = (const float*)d_in[0];
    const float* masks = (const float*)d_in[1];
    if (n_in >= 2 && in_sizes[0] == N_ * KK * KK * HO * WO &&
        in_sizes[1] == N_ * C_ * H_ * W_) {
        const float* tmp = feat; feat = masks; masks = tmp;
    }
    carafe_kernel<<<N_ * 128 * NCHUNK, NTHREADS>>>(feat, masks, (float*)d_out);
}

// round 13
// speedup vs baseline: 1.1029x; 1.1029x over previous
#include <cuda_runtime.h>
#include <cstdint>

// CARAFE: N=4, C=256, H=W=64, K=5, G=1, S=2  ->  out [4,256,128,128] f32
#define KK   5
#define N_   4
#define C_   256
#define H_   64
#define W_   64
#define HO   128
#define WO   128

#define TH_CELLS 4         // input cells per CTA (rows)
#define TW_CELLS 8         // input cells per CTA (cols)
#define PR 8               // patch rows = TH_CELLS + 4
#define PC 12              // patch cols = TW_CELLS + 4
#define PS4 13             // row stride in float4 units (odd stagger)
#define QUAD_F (PR * PS4 * 4)     // 416 floats per channel-quad patch
#define STAGE_F (2 * QUAD_F)      // 832 floats per 8-channel stage
#define NTHREADS 128
#define NCHUNK 2                  // channel split: 2 CTAs per tile
#define CHPC (C_ / NCHUNK)        // 128 channels per CTA
#define NSTAGE (CHPC / 8)         // 16 stages of 8 channels
#define NLOAD (8 * PR * PC)       // 768 feature elements per stage
#define LPT (NLOAD / NTHREADS)    // 6

typedef unsigned long long ull;

__device__ __forceinline__ ull pack2(float lo, float hi) {
    ull r;
    asm("mov.b64 %0, {%1, %2};" : "=l"(r) : "f"(lo), "f"(hi));
    return r;
}
__device__ __forceinline__ void unpack2(float& lo, float& hi, ull v) {
    asm("mov.b64 {%0, %1}, %2;" : "=f"(lo), "=f"(hi) : "l"(v));
}
__device__ __forceinline__ void ffma2(ull& d, ull a, ull b) {
    asm("fma.rn.f32x2 %0, %1, %2, %0;" : "+l"(d) : "l"(a), "l"(b));
}

__global__ void __launch_bounds__(NTHREADS, 4)
carafe_kernel(const float* __restrict__ feat, const float* __restrict__ masks,
              float* __restrict__ out)
{
    __shared__ __align__(16) float sbuf[2][STAGE_F];   // 2*832*4 = 6656 B

    const int t    = threadIdx.x;
    const int oh_l = t >> 4;          // 0..7  local output row
    const int ow_l = t & 15;          // 0..15 local output col
    const int hh   = oh_l >> 1;       // input cell row 0..3
    const int wwq  = ow_l >> 1;       // input cell col 0..7

    const int b     = blockIdx.x;     // 0..1023
    const int chunk = b & 1;          // 2 CTAs sharing a tile's masks are adjacent
    const int tidx  = (b >> 1) & 127;
    const int n     = b >> 8;
    const int th    = tidx >> 3;      // 0..15
    const int tw    = tidx & 7;       // 0..7
    const int h0    = th * TH_CELLS;
    const int w0    = tw * TW_CELLS;
    const int oh    = th * (2 * TH_CELLS) + oh_l;
    const int ow    = tw * (2 * TW_CELLS) + ow_l;

    // ---- per-thread masks (one output pixel), duplicated for channel-packed FFMA2 ----
    ull m[25];
    {
        const float* mb = masks + (size_t)n * 25 * (HO * WO) + (size_t)oh * WO + ow;
        #pragma unroll
        for (int k = 0; k < 25; ++k) {
            const float mv = __ldg(mb + (size_t)k * (HO * WO));
            m[k] = pack2(mv, mv);
        }
    }

    // ---- cooperative-load slots: channel-quad (float4) layout ----
    const float* fbase = feat + (size_t)n * (C_ * H_ * W_)
                              + (size_t)chunk * CHPC * (H_ * W_);
    int sofs[LPT], gofs[LPT];
    #pragma unroll
    for (int i = 0; i < LPT; ++i) {
        const int e   = t + i * NTHREADS;          // < 768
        const int ch  = e / (PR * PC);             // 0..7
        const int rem = e - ch * (PR * PC);
        const int r   = rem / PC;
        const int col = rem - r * PC;
        const int gr  = h0 - 2 + r;
        const int gc  = w0 - 2 + col;
        sofs[i] = (ch >> 2) * QUAD_F + r * (PS4 * 4) + col * 4 + (ch & 3);
        gofs[i] = ((unsigned)gr < (unsigned)H_ && (unsigned)gc < (unsigned)W_)
                      ? (ch * (H_ * W_) + gr * W_ + gc)
                      : -1;
    }

    float v[LPT];

    // prologue: stage 0 -> buffer 0
    #pragma unroll
    for (int i = 0; i < LPT; ++i)
        v[i] = (gofs[i] >= 0) ? __ldg(fbase + gofs[i]) : 0.f;
    #pragma unroll
    for (int i = 0; i < LPT; ++i)
        sbuf[0][sofs[i]] = v[i];
    __syncthreads();

    float* obase = out + (size_t)n * (C_ * HO * WO)
                       + (size_t)chunk * CHPC * (HO * WO)
                       + (size_t)oh * WO + ow;

    #pragma unroll 1
    for (int s = 0; s < NSTAGE; ++s) {
        // prefetch next stage's features (latency hidden under compute)
        if (s + 1 < NSTAGE) {
            const float* fb = fbase + (size_t)(s + 1) * 8 * (H_ * W_);
            #pragma unroll
            for (int i = 0; i < LPT; ++i)
                v[i] = (gofs[i] >= 0) ? __ldg(fb + gofs[i]) : 0.f;
        }

        // compute: 2 quads x 25 taps, LDS.128 feeding 2 FFMA2 directly (no repack)
        const float* sb = &sbuf[s & 1][0] + (hh * PS4 + wwq) * 4;
        ull a0 = 0, a1 = 0, a2 = 0, a3 = 0;
        #pragma unroll
        for (int ki = 0; ki < KK; ++ki) {
            #pragma unroll
            for (int kj = 0; kj < KK; ++kj) {
                const int k   = ki * KK + kj;
                const int off = (ki * PS4 + kj) * 4;
                const ulonglong2 fA = *(const ulonglong2*)(sb + off);
                const ulonglong2 fB = *(const ulonglong2*)(sb + QUAD_F + off);
                ffma2(a0, fA.x, m[k]);
                ffma2(a1, fA.y, m[k]);
                ffma2(a2, fB.x, m[k]);
                ffma2(a3, fB.y, m[k]);
            }
        }

        // stores: 8 channels, channel-strided (coalesced across the warp)
        {
            const int c0 = s * 8;
            float lo, hi;
            unpack2(lo, hi, a0);
            obase[(size_t)(c0 + 0) * (HO * WO)] = lo;
            obase[(size_t)(c0 + 1) * (HO * WO)] = hi;
            unpack2(lo, hi, a1);
            obase[(size_t)(c0 + 2) * (HO * WO)] = lo;
            obase[(size_t)(c0 + 3) * (HO * WO)] = hi;
            unpack2(lo, hi, a2);
            obase[(size_t)(c0 + 4) * (HO * WO)] = lo;
            obase[(size_t)(c0 + 5) * (HO * WO)] = hi;
            unpack2(lo, hi, a3);
            obase[(size_t)(c0 + 6) * (HO * WO)] = lo;
            obase[(size_t)(c0 + 7) * (HO * WO)] = hi;
        }

        // commit prefetched data to the other buffer
        if (s + 1 < NSTAGE) {
            float* dst = &sbuf[(s + 1) & 1][0];
            #pragma unroll
            for (int i = 0; i < LPT; ++i)
                dst[sofs[i]] = v[i];
        }
        __syncthreads();
    }
}

extern "C" void kernel_launch(void* const* d_in, const int* in_sizes, int n_in,
                              void* d_out, int out_size) {
    const float* feat  = (const float*)d_in[0];
    const float* masks = (const float*)d_in[1];
    if (n_in >= 2 && in_sizes[0] == N_ * KK * KK * HO * WO &&
        in_sizes[1] == N_ * C_ * H_ * W_) {
        const float* tmp = feat; feat = masks; masks = tmp;
    }
    carafe_kernel<<<N_ * 128 * NCHUNK, NTHREADS>>>(feat, masks, (float*)d_out);
}